// round 1
// baseline (speedup 1.0000x reference)
#include <cuda_runtime.h>
#include <math.h>

#define L_LEN   100000
#define B_ROWS  512
#define HALF    50000          // L/2 pooled elements per row
#define NOISE_STD 0.04f
#define NTHREADS 1024

// Precomputed per-position noise contribution to each pooled element:
// npool[j] = (noise[2j] + noise[2j+1]) * STD / 2. Row-invariant, L2-resident.
__device__ float g_npool[HALF];

__global__ void noise_pool_kernel(const float* __restrict__ noise) {
    int j = blockIdx.x * blockDim.x + threadIdx.x;
    if (j < HALF) {
        float2 n = reinterpret_cast<const float2*>(noise)[j];
        g_npool[j] = (n.x + n.y) * (0.5f * NOISE_STD);
    }
}

__global__ __launch_bounds__(NTHREADS, 1)
void triple_transform_kernel(const float* __restrict__ x,
                             const int* __restrict__ move_p,
                             float* __restrict__ out) {
    extern __shared__ float s_pool[];           // HALF floats (200 KB)
    __shared__ float rs[32], rq[32];
    __shared__ float s_mu, s_inv;

    const int b = blockIdx.x;
    const float* xr = x + (size_t)b * L_LEN;
    float2* outr = reinterpret_cast<float2*>(out + (size_t)b * L_LEN);

    int move = *move_p;
    move %= L_LEN; if (move < 0) move += L_LEN;

    float sum = 0.f, sumsq = 0.f;

    if ((move & 1) == 0) {
        // Fast path: even shift -> each pooled pair is one aligned float2,
        // wrap handled on the float2 index (no pair straddles the boundary).
        const float2* xr2 = reinterpret_cast<const float2*>(xr);
        const int moff = move >> 1;             // shift in float2 units
        for (int j = threadIdx.x; j < HALF; j += NTHREADS) {
            int i = j - moff;
            if (i < 0) i += HALF;
            float2 v = xr2[i];
            float p = 0.5f * (v.x + v.y) + g_npool[j];
            s_pool[j] = p;
            sum += p;
            sumsq += p * p;
        }
    } else {
        // Generic path: scalar loads, per-element wrap.
        for (int j = threadIdx.x; j < HALF; j += NTHREADS) {
            int i0 = 2 * j - move;
            if (i0 < 0) i0 += L_LEN;
            int i1 = i0 + 1;
            if (i1 >= L_LEN) i1 -= L_LEN;
            float p = 0.5f * (xr[i0] + xr[i1]) + g_npool[j];
            s_pool[j] = p;
            sum += p;
            sumsq += p * p;
        }
    }

    // Block reduction: warp shuffles, then warp 0 over 32 partials.
    #pragma unroll
    for (int o = 16; o; o >>= 1) {
        sum   += __shfl_down_sync(0xFFFFFFFFu, sum, o);
        sumsq += __shfl_down_sync(0xFFFFFFFFu, sumsq, o);
    }
    const int warp = threadIdx.x >> 5, lane = threadIdx.x & 31;
    if (lane == 0) { rs[warp] = sum; rq[warp] = sumsq; }
    __syncthreads();
    if (warp == 0) {
        float a = rs[lane];
        float q = rq[lane];
        #pragma unroll
        for (int o = 16; o; o >>= 1) {
            a += __shfl_down_sync(0xFFFFFFFFu, a, o);
            q += __shfl_down_sync(0xFFFFFFFFu, q, o);
        }
        if (lane == 0) {
            const float inv_n = 1.0f / (float)HALF;
            float mu  = a * inv_n;
            float var = fmaxf(q * inv_n - mu * mu, 0.f);
            s_mu  = mu;
            s_inv = rsqrtf(var);
        }
    }
    __syncthreads();

    const float mu = s_mu, inv = s_inv;
    for (int j = threadIdx.x; j < HALF; j += NTHREADS) {
        float v = (s_pool[j] - mu) * inv;
        outr[j] = make_float2(v, v);
    }
}

extern "C" void kernel_launch(void* const* d_in, const int* in_sizes, int n_in,
                              void* d_out, int out_size) {
    const float* x     = (const float*)d_in[0];
    const float* noise = (const float*)d_in[1];
    const int*   move  = (const int*)d_in[2];
    float* out = (float*)d_out;

    // Raise dynamic smem limit (idempotent; host-side attr set, capture-safe).
    cudaFuncSetAttribute(triple_transform_kernel,
                         cudaFuncAttributeMaxDynamicSharedMemorySize,
                         HALF * (int)sizeof(float));

    noise_pool_kernel<<<(HALF + 255) / 256, 256>>>(noise);
    triple_transform_kernel<<<B_ROWS, NTHREADS, HALF * sizeof(float)>>>(x, move, out);
}